// round 15
// baseline (speedup 1.0000x reference)
#include <cuda_runtime.h>
#include <cstdint>
#include <cstddef>

#define BB 8
#define LL 2048
#define HH 8
#define DD 64
#define EE 33
#define UU 40
#define SK 40
#define BHN (BB*HH)
#define ROWS (BHN*LL)

typedef unsigned long long ull;

// ---------------- static scratch ----------------
__device__ float2 g_qf [ROWS*EE];
__device__ float2 g_vf [ROWS*EE];
__device__ float4 g_kfC[(size_t)BHN*8*4096];   // [bh][chunk(8)][id*2+half]
__device__ float  g_k32[BHN*LL];
__device__ float  g_M  [ROWS];
__device__ int    g_top [BHN*UU];
__device__ int    g_slot[ROWS];
__device__ float2 g_upd [BHN*UU*EE];
__device__ float  g_vmt[BHN*DD];
__device__ float2 g_big [(size_t)BHN*UU*LL];

__device__ __forceinline__ void cpa16(void* s, const void* g) {
    unsigned sa = (unsigned)__cvta_generic_to_shared(s);
    asm volatile("cp.async.cg.shared.global [%0], [%1], 16;" :: "r"(sa), "l"(g));
}
__device__ __forceinline__ void cp_commit() {
    asm volatile("cp.async.commit_group;" ::: "memory");
}
__device__ __forceinline__ void cp_wait1() {
    asm volatile("cp.async.wait_group 1;" ::: "memory");
}
__device__ __forceinline__ void cp_wait0() {
    asm volatile("cp.async.wait_group 0;" ::: "memory");
}

// f32x2 packed helpers
__device__ __forceinline__ ull pk2(float lo, float hi) {
    ull r; asm("mov.b64 %0, {%1,%2};" : "=l"(r) : "f"(lo), "f"(hi)); return r;
}
__device__ __forceinline__ void upk2(ull x, float& lo, float& hi) {
    asm("mov.b64 {%0,%1}, %2;" : "=f"(lo), "=f"(hi) : "l"(x));
}
__device__ __forceinline__ ull fma2(ull a, ull b, ull c) {
    ull d; asm("fma.rn.f32x2 %0, %1, %2, %3;" : "=l"(d) : "l"(a), "l"(b), "l"(c)); return d;
}

// ---------------- K1: rfft, 4 rows/warp, register twiddles, shfl mirror ----------------
__global__ void k_rfft(const float* __restrict__ q,
                       const float* __restrict__ k,
                       const float* __restrict__ v)
{
    __shared__ float2 w32t[16], w64t[32];
    int tid = threadIdx.x;
    if (tid < 16) {
        float s, c;
        sincospif(tid * (1.0f/16.0f), &s, &c);
        w32t[tid] = make_float2(c, s);
    } else if (tid < 48) {
        float s, c;
        sincospif((tid - 16) * (1.0f/32.0f), &s, &c);
        w64t[tid - 16] = make_float2(c, s);
    }
    __syncthreads();
    int warp = tid >> 5, lane = tid & 31;
    float2 tw[5];
    #pragma unroll
    for (int s = 0; s < 5; ++s) {
        int hm = 16 >> s;
        tw[s] = w32t[(lane & (hm - 1)) << s];
    }
    int bin = __brev((unsigned)lane) >> 27;
    float2 w64 = w64t[bin];
    int mb   = (32 - bin) & 31;
    int srcl = __brev((unsigned)mb) >> 27;
    int which = blockIdx.y;
    const float* src = (which == 0) ? q : (which == 1) ? k : v;
    float2* out = (which == 0) ? g_qf : g_vf;
    #pragma unroll 1
    for (int i = 0; i < 4; ++i) {
        int r  = blockIdx.x * 32 + warp * 4 + i;
        int l  = r & (LL - 1);
        int bh = r >> 11;
        int b = bh >> 3, h = bh & 7;
        const float2* x2 = (const float2*)(src + (((size_t)b*LL + l)*HH + h) * DD);
        float2 z = x2[lane];
        float zr = z.x, zi = z.y;
        #pragma unroll
        for (int s = 0; s < 5; ++s) {
            int hm = 16 >> s;
            float orr = __shfl_xor_sync(0xffffffffu, zr, hm);
            float oii = __shfl_xor_sync(0xffffffffu, zi, hm);
            float2 w = tw[s];
            float dx = orr - zr, dy = oii - zi;
            float hr = dx*w.x + dy*w.y;
            float hi = dy*w.x - dx*w.y;
            float lr = zr + orr, li = zi + oii;
            bool top = (lane & hm) != 0;
            zr = top ? hr : lr;
            zi = top ? hi : li;
        }
        float Zmr = __shfl_sync(0xffffffffu, zr, srcl);
        float Zmi = __shfl_sync(0xffffffffu, zi, srcl);
        float Zer = 0.5f*(zr + Zmr), Zei = 0.5f*(zi - Zmi);
        float Zor = 0.5f*(zi + Zmi), Zoi = -0.5f*(zr - Zmr);
        float Xr = Zer + w64.x*Zor + w64.y*Zoi;
        float Xi = Zei + w64.x*Zoi - w64.y*Zor;
        if (which == 1) {
            int c = bin >> 2, half = (bin >> 1) & 1;
            float2* kc2 = (float2*)g_kfC;
            size_t idx = ((((size_t)(bh*8 + c)) << 12) + (size_t)l*2 + half)*2 + (bin & 1);
            kc2[idx] = make_float2(Xr, Xi);
            if (bin == 0) g_k32[bh*LL + l] = zr - zi;
        } else {
            out[(size_t)r*EE + bin] = make_float2(Xr, Xi);
            if (bin == 0) out[(size_t)r*EE + 32] = make_float2(zr - zi, 0.f);
        }
    }
}

// ---------------- K2b: time-domain v mean ----------------
__global__ void k_vmt(const float* __restrict__ v)
{
    __shared__ float part[8][64];
    int bh = blockIdx.x, b = bh >> 3, h = bh & 7;
    int tid = threadIdx.x;
    int d = tid & 63, g = tid >> 6;
    const float* base = v + (((size_t)b*LL)*HH + h) * DD + d;
    float acc = 0.f;
    #pragma unroll 8
    for (int i = g; i < LL; i += 8) acc += base[(size_t)i * (HH*DD)];
    part[g][d] = acc;
    __syncthreads();
    if (tid < 64) {
        float s = 0.f;
        #pragma unroll
        for (int g2 = 0; g2 < 8; ++g2) s += part[g2][tid];
        g_vmt[bh*DD + tid] = s * (1.0f/LL);
    }
}

// ---------------- K3: sampled QK -> M (smem keys + staged q) ----------------
#define MS_KBUF   131072
#define MS_SK32   (MS_KBUF)
#define MS_PT     (MS_KBUF + 8192)
#define MS_QS     (MS_KBUF + 8192 + 16384)
#define MS_SMEM   (MS_KBUF + 8192 + 16384 + 10240)
__global__ void __launch_bounds__(1024, 1) k_msample(const int* __restrict__ isamp)
{
    extern __shared__ char sm[];
    float4* kbuf = (float4*)sm;
    float*  sk32 = (float*)(sm + MS_SK32);
    float4* pt   = (float4*)(sm + MS_PT);
    float2* qs   = (float2*)(sm + MS_QS);

    int tid = threadIdx.x;
    int l0  = blockIdx.x * 256;
    int bh  = blockIdx.y;
    int sg  = tid & 3;
    int lq  = tid >> 2;
    int l   = l0 + lq;

    sk32[tid]        = g_k32[bh*LL + tid];
    sk32[tid + 1024] = g_k32[bh*LL + tid + 1024];

    const int* ip = isamp + l*SK + sg*10;
    int ids[10];
    #pragma unroll
    for (int i = 0; i < 10; ++i) ids[i] = ip[i];

    float q32 = g_qf[((size_t)(bh*LL + l))*EE + 32].x;

    const float4* kc = g_kfC + (((size_t)(bh*8)) << 12);
    #pragma unroll
    for (int it = 0; it < 4; ++it) {
        int lin = it*1024 + tid;
        int sw  = lin ^ ((lin >> 3) & 7);
        cpa16(&kbuf[sw], &kc[lin]);
    }
    cp_commit();

    float accR[10], accI[10];
    #pragma unroll
    for (int s = 0; s < 10; ++s) { accR[s] = 0.f; accI[s] = 0.f; }

    int qrow_s = tid >> 2, qbin_s = tid & 3;
    const float2* qsrc = g_qf + (size_t)(bh*LL + l0 + qrow_s)*EE + qbin_s;

    #pragma unroll 1
    for (int c = 0; c < 8; ++c) {
        qs[qrow_s*5 + qbin_s] = qsrc[4*c];
        int cur = (c & 1) << 12;
        if (c < 7) {
            const float4* src = kc + ((size_t)(c+1) << 12);
            int nb = ((c+1) & 1) << 12;
            #pragma unroll
            for (int it = 0; it < 4; ++it) {
                int lin = it*1024 + tid;
                int sw  = lin ^ ((lin >> 3) & 7);
                cpa16(&kbuf[nb + sw], &src[lin]);
            }
            cp_commit();
            cp_wait1();
        } else {
            cp_wait0();
        }
        __syncthreads();
        float2 q0 = qs[lq*5 + 0], q1 = qs[lq*5 + 1], q2 = qs[lq*5 + 2], q3 = qs[lq*5 + 3];
        #pragma unroll
        for (int s = 0; s < 10; ++s) {
            int id = ids[s];
            int p = id << 1, x = (id >> 2) & 7;
            float4 h0 = kbuf[cur + (p ^ x)];
            float4 h1 = kbuf[cur + ((p + 1) ^ x)];
            accR[s] = fmaf(q0.x, h0.x, accR[s]); accR[s] = fmaf(-q0.y, h0.y, accR[s]);
            accI[s] = fmaf(q0.x, h0.y, accI[s]); accI[s] = fmaf( q0.y, h0.x, accI[s]);
            accR[s] = fmaf(q1.x, h0.z, accR[s]); accR[s] = fmaf(-q1.y, h0.w, accR[s]);
            accI[s] = fmaf(q1.x, h0.w, accI[s]); accI[s] = fmaf( q1.y, h0.z, accI[s]);
            accR[s] = fmaf(q2.x, h1.x, accR[s]); accR[s] = fmaf(-q2.y, h1.y, accR[s]);
            accI[s] = fmaf(q2.x, h1.y, accI[s]); accI[s] = fmaf( q2.y, h1.x, accI[s]);
            accR[s] = fmaf(q3.x, h1.z, accR[s]); accR[s] = fmaf(-q3.y, h1.w, accR[s]);
            accI[s] = fmaf(q3.x, h1.w, accI[s]); accI[s] = fmaf( q3.y, h1.z, accI[s]);
        }
        __syncthreads();
    }
    #pragma unroll
    for (int s = 0; s < 10; ++s)
        accR[s] = fmaf(q32, sk32[ids[s]], accR[s]);

    float mr = -3.4e38f, mi = -3.4e38f, sr = 0.f, si = 0.f;
    #pragma unroll
    for (int s = 0; s < 10; ++s) {
        mr = fmaxf(mr, accR[s]); mi = fmaxf(mi, accI[s]);
        sr += accR[s];           si += accI[s];
    }
    pt[sg*256 + lq] = make_float4(mr, mi, sr, si);
    __syncthreads();
    if (tid < 256) {
        float4 a = pt[tid], b = pt[256 + tid], c2 = pt[512 + tid], d = pt[768 + tid];
        float MR = fmaxf(fmaxf(a.x, b.x), fmaxf(c2.x, d.x));
        float MI = fmaxf(fmaxf(a.y, b.y), fmaxf(c2.y, d.y));
        float SR = a.z + b.z + c2.z + d.z;
        float SI = a.w + b.w + c2.w + d.w;
        g_M[(size_t)bh*LL + l0 + tid] = MR + MI - (SR + SI) * (1.0f/LL);
    }
}

// ---------------- K4: top-40 per bh — warp select + parallel rank merge ----------------
__global__ void __launch_bounds__(256) k_topk()
{
    __shared__ float wlv[8][UU];
    __shared__ int   wli[8][UU];
    int bh = blockIdx.x, tid = threadIdx.x, lane = tid & 31, warp = tid >> 5;
    for (int i = tid; i < LL; i += 256)
        g_slot[bh*LL + i] = -1;

    // phase 1: warp w owns [w*256, w*256+256), 8 reg values/lane
    int base = warp * 256;
    float vals[8];
    #pragma unroll
    for (int k = 0; k < 8; ++k)
        vals[k] = g_M[bh*LL + base + lane + k*32];
    #pragma unroll 1
    for (int u = 0; u < UU; ++u) {
        float best = -3.4e38f; int bk = 0;
        #pragma unroll
        for (int k = 0; k < 8; ++k)
            if (vals[k] > best) { best = vals[k]; bk = k; }
        int bidx = base + lane + bk*32;
        float bv = best; int bi = bidx;
        #pragma unroll
        for (int o = 16; o; o >>= 1) {
            float ov = __shfl_xor_sync(0xffffffffu, bv, o);
            int   oi = __shfl_xor_sync(0xffffffffu, bi, o);
            if (ov > bv || (ov == bv && oi < bi)) { bv = ov; bi = oi; }
        }
        if (bi == bidx) vals[bk] = -3.4e38f;
        if (lane == 0) { wlv[warp][u] = bv; wli[warp][u] = bi; }
    }
    __syncthreads();

    // phase 2: parallel rank of ALL 320 candidates (grid-stride: 320 > 256 threads!)
    for (int t = tid; t < 8*UU; t += 256) {
        int w = t / UU, pos = t - w*UU;
        float v = wlv[w][pos];
        int idx = wli[w][pos];
        int rank = pos;
        #pragma unroll
        for (int w2 = 0; w2 < 8; ++w2) {
            if (w2 == w) continue;
            int lo = 0, hi = UU;
            while (lo < hi) {
                int mid = (lo + hi) >> 1;
                float mv = wlv[w2][mid];
                int   mi = wli[w2][mid];
                if (mv > v || (mv == v && mi < idx)) lo = mid + 1;
                else hi = mid;
            }
            rank += lo;
        }
        if (rank < UU) {
            g_top[bh*UU + rank] = idx;
            g_slot[bh*LL + idx] = rank;
        }
    }
}

// ---------------- K5: full scores, f32x2 packed over u-pairs ----------------
__global__ void __launch_bounds__(512) k_scores()
{
    __shared__ ull sPx[5][EE];    // (qx_{2p}, qx_{2p+1})
    __shared__ ull sPy[5][EE];    // (qy0, qy1)
    __shared__ ull sNy[5][EE];    // (-qy0, -qy1)
    int bh = blockIdx.z;
    int ug = blockIdx.y;     // 0..3 (10 u each)
    int jt = blockIdx.x;     // 0..3
    int tid = threadIdx.x;
    for (int t = tid; t < 5*EE; t += 512) {
        int p = t / EE, e = t - p*EE;
        int qa = g_top[bh*UU + ug*10 + 2*p];
        int qb = g_top[bh*UU + ug*10 + 2*p + 1];
        float2 A = g_qf[((size_t)bh*LL + qa)*EE + e];
        float2 B = g_qf[((size_t)bh*LL + qb)*EE + e];
        sPx[p][e] = pk2(A.x, B.x);
        sPy[p][e] = pk2(A.y, B.y);
        sNy[p][e] = pk2(-A.y, -B.y);
    }
    __syncthreads();
    int j = jt*512 + tid;
    ull accR2[5], accI2[5];
    #pragma unroll
    for (int p = 0; p < 5; ++p) { accR2[p] = 0ull; accI2[p] = 0ull; }
    const float4* kc = g_kfC + (((size_t)(bh*8)) << 12);
    #pragma unroll 1
    for (int c = 0; c < 8; ++c) {
        float4 h0 = kc[((size_t)c << 12) + j*2];
        float4 h1 = kc[((size_t)c << 12) + j*2 + 1];
        float kx[4] = {h0.x, h0.z, h1.x, h1.z};
        float ky[4] = {h0.y, h0.w, h1.y, h1.w};
        #pragma unroll
        for (int b = 0; b < 4; ++b) {
            ull kxx = pk2(kx[b], kx[b]);
            ull kyy = pk2(ky[b], ky[b]);
            int e = 4*c + b;
            #pragma unroll
            for (int p = 0; p < 5; ++p) {
                ull Px = sPx[p][e], Py = sPy[p][e], Ny = sNy[p][e];
                accR2[p] = fma2(Px, kxx, accR2[p]);
                accR2[p] = fma2(Ny, kyy, accR2[p]);
                accI2[p] = fma2(Px, kyy, accI2[p]);
                accI2[p] = fma2(Py, kxx, accI2[p]);
            }
        }
    }
    {   // e = 32: k imag exactly 0
        float k32 = g_k32[bh*LL + j];
        ull kk = pk2(k32, k32);
        #pragma unroll
        for (int p = 0; p < 5; ++p) {
            accR2[p] = fma2(sPx[p][32], kk, accR2[p]);
            accI2[p] = fma2(sPy[p][32], kk, accI2[p]);
        }
    }
    const float sc = 0.125f;
    #pragma unroll
    for (int p = 0; p < 5; ++p) {
        float r0, r1, i0, i1;
        upk2(accR2[p], r0, r1);
        upk2(accI2[p], i0, i1);
        g_big[((size_t)bh*UU + ug*10 + 2*p)*LL + j]     = make_float2(r0*sc, i0*sc);
        g_big[((size_t)bh*UU + ug*10 + 2*p + 1)*LL + j] = make_float2(r1*sc, i1*sc);
    }
}

// ---------------- K6: fused softmax + upd (4 u per block, f32x2 upd) ----------------
#define SMU_SMEM (65536 + 16896 + 128)
__global__ void __launch_bounds__(512) k_smupd()
{
    extern __shared__ char smc[];
    float2* p    = (float2*)smc;
    float2* accs = (float2*)(smc + 65536);
    float2* mxs  = (float2*)(smc + 65536 + 16896);
    int bh = blockIdx.y, ug = blockIdx.x;
    int tid = threadIdx.x, warp = tid >> 5, lane = tid & 31;

    const float2* gb = g_big + ((size_t)bh*UU + ug*4)*LL;
    for (int i = tid; i < 4*LL; i += 512)
        p[i] = gb[i];
    __syncthreads();

    int su = warp >> 2, qt = warp & 3;
    float2* row = p + (su << 11) + (qt << 9);
    float mr = -3.4e38f, mi = -3.4e38f;
    #pragma unroll 8
    for (int k2 = 0; k2 < 16; ++k2) {
        float2 vv = row[lane + k2*32];
        mr = fmaxf(mr, vv.x); mi = fmaxf(mi, vv.y);
    }
    #pragma unroll
    for (int o = 16; o; o >>= 1) {
        mr = fmaxf(mr, __shfl_xor_sync(0xffffffffu, mr, o));
        mi = fmaxf(mi, __shfl_xor_sync(0xffffffffu, mi, o));
    }
    if (lane == 0) mxs[warp] = make_float2(mr, mi);
    __syncthreads();
    {
        float2 a = mxs[su*4], b = mxs[su*4+1], c = mxs[su*4+2], d = mxs[su*4+3];
        mr = fmaxf(fmaxf(a.x, b.x), fmaxf(c.x, d.x));
        mi = fmaxf(fmaxf(a.y, b.y), fmaxf(c.y, d.y));
    }
    __syncthreads();
    float sr = 0.f, si = 0.f;
    #pragma unroll 8
    for (int k2 = 0; k2 < 16; ++k2) {
        float2 vv = row[lane + k2*32];
        float er = __expf(vv.x - mr);
        float ei = __expf(vv.y - mi);
        row[lane + k2*32] = make_float2(er, ei);
        sr += er; si += ei;
    }
    #pragma unroll
    for (int o = 16; o; o >>= 1) {
        sr += __shfl_xor_sync(0xffffffffu, sr, o);
        si += __shfl_xor_sync(0xffffffffu, si, o);
    }
    if (lane == 0) mxs[warp] = make_float2(sr, si);
    __syncthreads();
    {
        float2 a = mxs[su*4], b = mxs[su*4+1], c = mxs[su*4+2], d = mxs[su*4+3];
        float inr = 1.0f / (a.x + b.x + c.x + d.x);
        float ini = 1.0f / (a.y + b.y + c.y + d.y);
        #pragma unroll 8
        for (int k2 = 0; k2 < 16; ++k2) {
            float2 vv = row[lane + k2*32];
            row[lane + k2*32] = make_float2(vv.x * inr, vv.y * ini);
        }
    }
    __syncthreads();

    // upd main: packed f32x2 — (pr,pi)*(vr,vi) accumulates both channels at once
    ull acc2[4];
    #pragma unroll
    for (int u = 0; u < 4; ++u) acc2[u] = 0ull;
    const ull* vb2 = (const ull*)(g_vf + (size_t)bh*LL*EE);
    const ull* p2  = (const ull*)p;
    for (int l = warp; l < LL; l += 16) {
        ull v2 = vb2[(size_t)l*EE + lane];
        #pragma unroll
        for (int u = 0; u < 4; ++u)
            acc2[u] = fma2(p2[(u << 11) + l], v2, acc2[u]);
    }
    float s32[4];
    #pragma unroll
    for (int u = 0; u < 4; ++u) s32[u] = 0.f;
    const float2* vb = g_vf + (size_t)bh*LL*EE;
    for (int l = tid; l < LL; l += 512) {
        float v32r = vb[(size_t)l*EE + 32].x;
        #pragma unroll
        for (int u = 0; u < 4; ++u)
            s32[u] = fmaf(p[(u << 11) + l].x, v32r, s32[u]);
    }
    #pragma unroll
    for (int o = 16; o; o >>= 1) {
        #pragma unroll
        for (int u = 0; u < 4; ++u)
            s32[u] += __shfl_xor_sync(0xffffffffu, s32[u], o);
    }
    #pragma unroll
    for (int u = 0; u < 4; ++u) {
        float aR, aI;
        upk2(acc2[u], aR, aI);
        accs[(warp*4 + u)*EE + lane] = make_float2(aR, aI);
        if (lane == 0) accs[(warp*4 + u)*EE + 32] = make_float2(s32[u], 0.f);
    }
    __syncthreads();
    for (int t = tid; t < 4*EE; t += 512) {
        int u = t / EE, e = t - u*EE;
        float ssr = 0.f, ssi = 0.f;
        #pragma unroll
        for (int w = 0; w < 16; ++w) {
            float2 a = accs[(w*4 + u)*EE + e];
            ssr += a.x; ssi += a.y;
        }
        g_upd[((size_t)bh*UU + ug*4 + u)*EE + e] = make_float2(ssr, ssi);
    }
}

// ---------------- K7: scatter + irfft, 4 rows per warp ----------------
__global__ void k_out(float* __restrict__ out)
{
    __shared__ float tc[64], ts[64];
    __shared__ float2 ub[8][EE];
    int tid = threadIdx.x;
    if (tid < 64) {
        float s, c;
        sincospif(tid * (1.0f/32.0f), &s, &c);
        tc[tid] = c; ts[tid] = s;
    }
    __syncthreads();
    int warp = tid >> 5, lane = tid & 31;
    #pragma unroll 1
    for (int i = 0; i < 4; ++i) {
        int r = blockIdx.x * 32 + warp * 4 + i;
        int bh = r >> 11;
        int slot = g_slot[r];
        float* op = out + (size_t)r * DD;
        if (slot < 0) {
            op[lane]      = g_vmt[bh*DD + lane];
            op[lane + 32] = g_vmt[bh*DD + lane + 32];
        } else {
            const float2* X = g_upd + ((size_t)bh*UU + slot)*EE;
            ub[warp][lane] = X[lane];
            if (lane == 0) ub[warp][32] = X[32];
            __syncwarp();
            float a0 = ub[warp][0].x;
            float a32 = ub[warp][32].x;
            float sgn = (lane & 1) ? -a32 : a32;
            float acc1 = a0 + sgn, acc2 = a0 + sgn;
            #pragma unroll
            for (int e = 1; e < 32; ++e) {
                float2 Xe = ub[warp][e];
                int j1 = (e * lane) & 63;
                int j2 = (e * (lane + 32)) & 63;
                acc1 += 2.f * (Xe.x*tc[j1] - Xe.y*ts[j1]);
                acc2 += 2.f * (Xe.x*tc[j2] - Xe.y*ts[j2]);
            }
            op[lane]      = acc1 * (1.0f/64.0f);
            op[lane + 32] = acc2 * (1.0f/64.0f);
            __syncwarp();
        }
    }
}

// ---------------- launch ----------------
extern "C" void kernel_launch(void* const* d_in, const int* in_sizes, int n_in,
                              void* d_out, int out_size)
{
    (void)in_sizes; (void)n_in; (void)out_size;
    const float* q = (const float*)d_in[0];
    const float* k = (const float*)d_in[1];
    const float* v = (const float*)d_in[2];
    const int* isamp = (const int*)d_in[4];
    float* out = (float*)d_out;

    cudaFuncSetAttribute(k_msample, cudaFuncAttributeMaxDynamicSharedMemorySize, MS_SMEM);
    cudaFuncSetAttribute(k_smupd,   cudaFuncAttributeMaxDynamicSharedMemorySize, SMU_SMEM);

    k_rfft     <<<dim3(ROWS/32, 3), 256>>>(q, k, v);
    k_vmt      <<<BHN, 512>>>(v);
    k_msample  <<<dim3(LL/256, BHN), 1024, MS_SMEM>>>(isamp);
    k_topk     <<<BHN, 256>>>();
    k_scores   <<<dim3(4, 4, BHN), 512>>>();
    k_smupd    <<<dim3(10, BHN), 512, SMU_SMEM>>>();
    k_out      <<<ROWS/32, 256>>>(out);
}

// round 16
// speedup vs baseline: 1.0177x; 1.0177x over previous
#include <cuda_runtime.h>
#include <cstdint>
#include <cstddef>

#define BB 8
#define LL 2048
#define HH 8
#define DD 64
#define EE 33
#define UU 40
#define SK 40
#define BHN (BB*HH)
#define ROWS (BHN*LL)

typedef unsigned long long ull;

// ---------------- static scratch ----------------
__device__ float2 g_qf [ROWS*EE];
__device__ float2 g_vf [ROWS*EE];
__device__ float4 g_kfC[(size_t)BHN*8*4096];   // [bh][chunk(8)][id*2+half]
__device__ float  g_k32[BHN*LL];
__device__ float  g_M  [ROWS];
__device__ int    g_top [BHN*UU];
__device__ int    g_slot[ROWS];
__device__ float2 g_upd [BHN*UU*EE];
__device__ float  g_vmt[BHN*DD];
__device__ float2 g_big [(size_t)BHN*UU*LL];

__device__ __forceinline__ void cpa16(void* s, const void* g) {
    unsigned sa = (unsigned)__cvta_generic_to_shared(s);
    asm volatile("cp.async.cg.shared.global [%0], [%1], 16;" :: "r"(sa), "l"(g));
}
__device__ __forceinline__ void cp_commit() {
    asm volatile("cp.async.commit_group;" ::: "memory");
}
__device__ __forceinline__ void cp_wait1() {
    asm volatile("cp.async.wait_group 1;" ::: "memory");
}
__device__ __forceinline__ void cp_wait0() {
    asm volatile("cp.async.wait_group 0;" ::: "memory");
}
__device__ __forceinline__ void upk2(ull x, float& lo, float& hi) {
    asm("mov.b64 {%0,%1}, %2;" : "=f"(lo), "=f"(hi) : "l"(x));
}
__device__ __forceinline__ ull fma2(ull a, ull b, ull c) {
    ull d; asm("fma.rn.f32x2 %0, %1, %2, %3;" : "=l"(d) : "l"(a), "l"(b), "l"(c)); return d;
}

// ---------------- K1: rfft, 4 rows/warp, register twiddles, shfl mirror ----------------
__global__ void k_rfft(const float* __restrict__ q,
                       const float* __restrict__ k,
                       const float* __restrict__ v)
{
    __shared__ float2 w32t[16], w64t[32];
    int tid = threadIdx.x;
    if (tid < 16) {
        float s, c;
        sincospif(tid * (1.0f/16.0f), &s, &c);
        w32t[tid] = make_float2(c, s);
    } else if (tid < 48) {
        float s, c;
        sincospif((tid - 16) * (1.0f/32.0f), &s, &c);
        w64t[tid - 16] = make_float2(c, s);
    }
    __syncthreads();
    int warp = tid >> 5, lane = tid & 31;
    float2 tw[5];
    #pragma unroll
    for (int s = 0; s < 5; ++s) {
        int hm = 16 >> s;
        tw[s] = w32t[(lane & (hm - 1)) << s];
    }
    int bin = __brev((unsigned)lane) >> 27;
    float2 w64 = w64t[bin];
    int mb   = (32 - bin) & 31;
    int srcl = __brev((unsigned)mb) >> 27;
    int which = blockIdx.y;
    const float* src = (which == 0) ? q : (which == 1) ? k : v;
    float2* out = (which == 0) ? g_qf : g_vf;
    #pragma unroll 1
    for (int i = 0; i < 4; ++i) {
        int r  = blockIdx.x * 32 + warp * 4 + i;
        int l  = r & (LL - 1);
        int bh = r >> 11;
        int b = bh >> 3, h = bh & 7;
        const float2* x2 = (const float2*)(src + (((size_t)b*LL + l)*HH + h) * DD);
        float2 z = x2[lane];
        float zr = z.x, zi = z.y;
        #pragma unroll
        for (int s = 0; s < 5; ++s) {
            int hm = 16 >> s;
            float orr = __shfl_xor_sync(0xffffffffu, zr, hm);
            float oii = __shfl_xor_sync(0xffffffffu, zi, hm);
            float2 w = tw[s];
            float dx = orr - zr, dy = oii - zi;
            float hr = dx*w.x + dy*w.y;
            float hi = dy*w.x - dx*w.y;
            float lr = zr + orr, li = zi + oii;
            bool top = (lane & hm) != 0;
            zr = top ? hr : lr;
            zi = top ? hi : li;
        }
        float Zmr = __shfl_sync(0xffffffffu, zr, srcl);
        float Zmi = __shfl_sync(0xffffffffu, zi, srcl);
        float Zer = 0.5f*(zr + Zmr), Zei = 0.5f*(zi - Zmi);
        float Zor = 0.5f*(zi + Zmi), Zoi = -0.5f*(zr - Zmr);
        float Xr = Zer + w64.x*Zor + w64.y*Zoi;
        float Xi = Zei + w64.x*Zoi - w64.y*Zor;
        if (which == 1) {
            int c = bin >> 2, half = (bin >> 1) & 1;
            float2* kc2 = (float2*)g_kfC;
            size_t idx = ((((size_t)(bh*8 + c)) << 12) + (size_t)l*2 + half)*2 + (bin & 1);
            kc2[idx] = make_float2(Xr, Xi);
            if (bin == 0) g_k32[bh*LL + l] = zr - zi;
        } else {
            out[(size_t)r*EE + bin] = make_float2(Xr, Xi);
            if (bin == 0) out[(size_t)r*EE + 32] = make_float2(zr - zi, 0.f);
        }
    }
}

// ---------------- K2b: time-domain v mean ----------------
__global__ void k_vmt(const float* __restrict__ v)
{
    __shared__ float part[8][64];
    int bh = blockIdx.x, b = bh >> 3, h = bh & 7;
    int tid = threadIdx.x;
    int d = tid & 63, g = tid >> 6;
    const float* base = v + (((size_t)b*LL)*HH + h) * DD + d;
    float acc = 0.f;
    #pragma unroll 8
    for (int i = g; i < LL; i += 8) acc += base[(size_t)i * (HH*DD)];
    part[g][d] = acc;
    __syncthreads();
    if (tid < 64) {
        float s = 0.f;
        #pragma unroll
        for (int g2 = 0; g2 < 8; ++g2) s += part[g2][tid];
        g_vmt[bh*DD + tid] = s * (1.0f/LL);
    }
}

// ---------------- K3: sampled QK -> M (smem keys + staged q) ----------------
#define MS_KBUF   131072
#define MS_SK32   (MS_KBUF)
#define MS_PT     (MS_KBUF + 8192)
#define MS_QS     (MS_KBUF + 8192 + 16384)
#define MS_SMEM   (MS_KBUF + 8192 + 16384 + 10240)
__global__ void __launch_bounds__(1024, 1) k_msample(const int* __restrict__ isamp)
{
    extern __shared__ char sm[];
    float4* kbuf = (float4*)sm;
    float*  sk32 = (float*)(sm + MS_SK32);
    float4* pt   = (float4*)(sm + MS_PT);
    float2* qs   = (float2*)(sm + MS_QS);

    int tid = threadIdx.x;
    int l0  = blockIdx.x * 256;
    int bh  = blockIdx.y;
    int sg  = tid & 3;
    int lq  = tid >> 2;
    int l   = l0 + lq;

    sk32[tid]        = g_k32[bh*LL + tid];
    sk32[tid + 1024] = g_k32[bh*LL + tid + 1024];

    const int* ip = isamp + l*SK + sg*10;
    int ids[10];
    #pragma unroll
    for (int i = 0; i < 10; ++i) ids[i] = ip[i];

    float q32 = g_qf[((size_t)(bh*LL + l))*EE + 32].x;

    const float4* kc = g_kfC + (((size_t)(bh*8)) << 12);
    #pragma unroll
    for (int it = 0; it < 4; ++it) {
        int lin = it*1024 + tid;
        int sw  = lin ^ ((lin >> 3) & 7);
        cpa16(&kbuf[sw], &kc[lin]);
    }
    cp_commit();

    float accR[10], accI[10];
    #pragma unroll
    for (int s = 0; s < 10; ++s) { accR[s] = 0.f; accI[s] = 0.f; }

    int qrow_s = tid >> 2, qbin_s = tid & 3;
    const float2* qsrc = g_qf + (size_t)(bh*LL + l0 + qrow_s)*EE + qbin_s;

    #pragma unroll 1
    for (int c = 0; c < 8; ++c) {
        qs[qrow_s*5 + qbin_s] = qsrc[4*c];
        int cur = (c & 1) << 12;
        if (c < 7) {
            const float4* src = kc + ((size_t)(c+1) << 12);
            int nb = ((c+1) & 1) << 12;
            #pragma unroll
            for (int it = 0; it < 4; ++it) {
                int lin = it*1024 + tid;
                int sw  = lin ^ ((lin >> 3) & 7);
                cpa16(&kbuf[nb + sw], &src[lin]);
            }
            cp_commit();
            cp_wait1();
        } else {
            cp_wait0();
        }
        __syncthreads();
        float2 q0 = qs[lq*5 + 0], q1 = qs[lq*5 + 1], q2 = qs[lq*5 + 2], q3 = qs[lq*5 + 3];
        #pragma unroll
        for (int s = 0; s < 10; ++s) {
            int id = ids[s];
            int p = id << 1, x = (id >> 2) & 7;
            float4 h0 = kbuf[cur + (p ^ x)];
            float4 h1 = kbuf[cur + ((p + 1) ^ x)];
            accR[s] = fmaf(q0.x, h0.x, accR[s]); accR[s] = fmaf(-q0.y, h0.y, accR[s]);
            accI[s] = fmaf(q0.x, h0.y, accI[s]); accI[s] = fmaf( q0.y, h0.x, accI[s]);
            accR[s] = fmaf(q1.x, h0.z, accR[s]); accR[s] = fmaf(-q1.y, h0.w, accR[s]);
            accI[s] = fmaf(q1.x, h0.w, accI[s]); accI[s] = fmaf( q1.y, h0.z, accI[s]);
            accR[s] = fmaf(q2.x, h1.x, accR[s]); accR[s] = fmaf(-q2.y, h1.y, accR[s]);
            accI[s] = fmaf(q2.x, h1.y, accI[s]); accI[s] = fmaf( q2.y, h1.x, accI[s]);
            accR[s] = fmaf(q3.x, h1.z, accR[s]); accR[s] = fmaf(-q3.y, h1.w, accR[s]);
            accI[s] = fmaf(q3.x, h1.w, accI[s]); accI[s] = fmaf( q3.y, h1.z, accI[s]);
        }
        __syncthreads();
    }
    #pragma unroll
    for (int s = 0; s < 10; ++s)
        accR[s] = fmaf(q32, sk32[ids[s]], accR[s]);

    float mr = -3.4e38f, mi = -3.4e38f, sr = 0.f, si = 0.f;
    #pragma unroll
    for (int s = 0; s < 10; ++s) {
        mr = fmaxf(mr, accR[s]); mi = fmaxf(mi, accI[s]);
        sr += accR[s];           si += accI[s];
    }
    pt[sg*256 + lq] = make_float4(mr, mi, sr, si);
    __syncthreads();
    if (tid < 256) {
        float4 a = pt[tid], b = pt[256 + tid], c2 = pt[512 + tid], d = pt[768 + tid];
        float MR = fmaxf(fmaxf(a.x, b.x), fmaxf(c2.x, d.x));
        float MI = fmaxf(fmaxf(a.y, b.y), fmaxf(c2.y, d.y));
        float SR = a.z + b.z + c2.z + d.z;
        float SI = a.w + b.w + c2.w + d.w;
        g_M[(size_t)bh*LL + l0 + tid] = MR + MI - (SR + SI) * (1.0f/LL);
    }
}

// ---------------- K4: top-40 per bh — warp-local select + single-warp merge ----------------
__global__ void __launch_bounds__(256) k_topk()
{
    __shared__ float wlv[8][UU];
    __shared__ int   wli[8][UU];
    int bh = blockIdx.x, tid = threadIdx.x, lane = tid & 31, warp = tid >> 5;
    for (int i = tid; i < LL; i += 256)
        g_slot[bh*LL + i] = -1;

    int base = warp * 256;
    float vals[8];
    #pragma unroll
    for (int k = 0; k < 8; ++k)
        vals[k] = g_M[bh*LL + base + lane + k*32];
    #pragma unroll 1
    for (int u = 0; u < UU; ++u) {
        float best = -3.4e38f; int bk = 0;
        #pragma unroll
        for (int k = 0; k < 8; ++k)
            if (vals[k] > best) { best = vals[k]; bk = k; }
        int bidx = base + lane + bk*32;
        float bv = best; int bi = bidx;
        #pragma unroll
        for (int o = 16; o; o >>= 1) {
            float ov = __shfl_xor_sync(0xffffffffu, bv, o);
            int   oi = __shfl_xor_sync(0xffffffffu, bi, o);
            if (ov > bv || (ov == bv && oi < bi)) { bv = ov; bi = oi; }
        }
        if (bi == bidx) vals[bk] = -3.4e38f;
        if (lane == 0) { wlv[warp][u] = bv; wli[warp][u] = bi; }
    }
    __syncthreads();

    if (warp == 0) {
        int ptr = 0;
        #pragma unroll 1
        for (int u = 0; u < UU; ++u) {
            float hv = (lane < 8) ? wlv[lane][ptr] : -3.4e38f;
            int   hi = (lane < 8) ? wli[lane][ptr] : (1 << 30);
            float rv = hv; int ri = hi;
            #pragma unroll
            for (int o = 4; o; o >>= 1) {
                float ov = __shfl_xor_sync(0xffffffffu, rv, o);
                int   oi = __shfl_xor_sync(0xffffffffu, ri, o);
                if (ov > rv || (ov == rv && oi < ri)) { rv = ov; ri = oi; }
            }
            rv = __shfl_sync(0xffffffffu, rv, 0);
            ri = __shfl_sync(0xffffffffu, ri, 0);
            if (lane < 8 && ri == hi) ptr++;
            if (lane == 0) {
                g_top[bh*UU + u] = ri;
                g_slot[bh*LL + ri] = u;
            }
        }
    }
}

// ---------------- K5: full scores from chunked keys, 10-u register blocked ----------------
__global__ void __launch_bounds__(512) k_scores()
{
    __shared__ float2 shq[10][EE];
    int bh = blockIdx.z;
    int ug = blockIdx.y;
    int jt = blockIdx.x;
    int tid = threadIdx.x;
    for (int t = tid; t < 10*EE; t += 512) {
        int ul = t / EE, e = t - ul*EE;
        int qi = g_top[bh*UU + ug*10 + ul];
        shq[ul][e] = g_qf[((size_t)bh*LL + qi)*EE + e];
    }
    __syncthreads();
    int j = jt*512 + tid;
    float accR[10], accI[10];
    #pragma unroll
    for (int u = 0; u < 10; ++u) { accR[u] = 0.f; accI[u] = 0.f; }
    const float4* kc = g_kfC + (((size_t)(bh*8)) << 12);
    #pragma unroll 1
    for (int c = 0; c < 8; ++c) {
        float4 h0 = kc[((size_t)c << 12) + j*2];
        float4 h1 = kc[((size_t)c << 12) + j*2 + 1];
        #pragma unroll
        for (int u = 0; u < 10; ++u) {
            float2 q0 = shq[u][4*c], q1 = shq[u][4*c+1], q2 = shq[u][4*c+2], q3 = shq[u][4*c+3];
            accR[u] = fmaf(q0.x, h0.x, accR[u]); accR[u] = fmaf(-q0.y, h0.y, accR[u]);
            accI[u] = fmaf(q0.x, h0.y, accI[u]); accI[u] = fmaf( q0.y, h0.x, accI[u]);
            accR[u] = fmaf(q1.x, h0.z, accR[u]); accR[u] = fmaf(-q1.y, h0.w, accR[u]);
            accI[u] = fmaf(q1.x, h0.w, accI[u]); accI[u] = fmaf( q1.y, h0.z, accI[u]);
            accR[u] = fmaf(q2.x, h1.x, accR[u]); accR[u] = fmaf(-q2.y, h1.y, accR[u]);
            accI[u] = fmaf(q2.x, h1.y, accI[u]); accI[u] = fmaf( q2.y, h1.x, accI[u]);
            accR[u] = fmaf(q3.x, h1.z, accR[u]); accR[u] = fmaf(-q3.y, h1.w, accR[u]);
            accI[u] = fmaf(q3.x, h1.w, accI[u]); accI[u] = fmaf( q3.y, h1.z, accI[u]);
        }
    }
    {
        float k32 = g_k32[bh*LL + j];
        #pragma unroll
        for (int u = 0; u < 10; ++u) {
            float2 qv = shq[u][32];
            accR[u] = fmaf(qv.x, k32, accR[u]);
            accI[u] = fmaf(qv.y, k32, accI[u]);
        }
    }
    const float sc = 0.125f;
    #pragma unroll
    for (int u = 0; u < 10; ++u)
        g_big[((size_t)bh*UU + ug*10 + u)*LL + j] = make_float2(accR[u]*sc, accI[u]*sc);
}

// ---------------- K6: fused softmax + upd (4 u per block, f32x2 upd loop) ----------------
#define SMU_SMEM (65536 + 16896 + 128)
__global__ void __launch_bounds__(512) k_smupd()
{
    extern __shared__ char smc[];
    float2* p    = (float2*)smc;
    float2* accs = (float2*)(smc + 65536);
    float2* mxs  = (float2*)(smc + 65536 + 16896);
    int bh = blockIdx.y, ug = blockIdx.x;
    int tid = threadIdx.x, warp = tid >> 5, lane = tid & 31;

    const float2* gb = g_big + ((size_t)bh*UU + ug*4)*LL;
    for (int i = tid; i < 4*LL; i += 512)
        p[i] = gb[i];
    __syncthreads();

    int su = warp >> 2, qt = warp & 3;
    float2* row = p + (su << 11) + (qt << 9);
    float mr = -3.4e38f, mi = -3.4e38f;
    #pragma unroll 8
    for (int k2 = 0; k2 < 16; ++k2) {
        float2 vv = row[lane + k2*32];
        mr = fmaxf(mr, vv.x); mi = fmaxf(mi, vv.y);
    }
    #pragma unroll
    for (int o = 16; o; o >>= 1) {
        mr = fmaxf(mr, __shfl_xor_sync(0xffffffffu, mr, o));
        mi = fmaxf(mi, __shfl_xor_sync(0xffffffffu, mi, o));
    }
    if (lane == 0) mxs[warp] = make_float2(mr, mi);
    __syncthreads();
    {
        float2 a = mxs[su*4], b = mxs[su*4+1], c = mxs[su*4+2], d = mxs[su*4+3];
        mr = fmaxf(fmaxf(a.x, b.x), fmaxf(c.x, d.x));
        mi = fmaxf(fmaxf(a.y, b.y), fmaxf(c.y, d.y));
    }
    __syncthreads();
    float sr = 0.f, si = 0.f;
    #pragma unroll 8
    for (int k2 = 0; k2 < 16; ++k2) {
        float2 vv = row[lane + k2*32];
        float er = __expf(vv.x - mr);
        float ei = __expf(vv.y - mi);
        row[lane + k2*32] = make_float2(er, ei);
        sr += er; si += ei;
    }
    #pragma unroll
    for (int o = 16; o; o >>= 1) {
        sr += __shfl_xor_sync(0xffffffffu, sr, o);
        si += __shfl_xor_sync(0xffffffffu, si, o);
    }
    if (lane == 0) mxs[warp] = make_float2(sr, si);
    __syncthreads();
    {
        float2 a = mxs[su*4], b = mxs[su*4+1], c = mxs[su*4+2], d = mxs[su*4+3];
        float inr = 1.0f / (a.x + b.x + c.x + d.x);
        float ini = 1.0f / (a.y + b.y + c.y + d.y);
        #pragma unroll 8
        for (int k2 = 0; k2 < 16; ++k2) {
            float2 vv = row[lane + k2*32];
            row[lane + k2*32] = make_float2(vv.x * inr, vv.y * ini);
        }
    }
    __syncthreads();

    // upd main: naturally-paired f32x2 — (pr,pi)*(vr,vi), loads unchanged (64-bit)
    ull acc2[4];
    #pragma unroll
    for (int u = 0; u < 4; ++u) acc2[u] = 0ull;
    const ull* vb2 = (const ull*)(g_vf + (size_t)bh*LL*EE);
    const ull* p2  = (const ull*)p;
    for (int l = warp; l < LL; l += 16) {
        ull v2 = vb2[(size_t)l*EE + lane];
        #pragma unroll
        for (int u = 0; u < 4; ++u)
            acc2[u] = fma2(p2[(u << 11) + l], v2, acc2[u]);
    }
    float s32[4];
    #pragma unroll
    for (int u = 0; u < 4; ++u) s32[u] = 0.f;
    const float2* vb = g_vf + (size_t)bh*LL*EE;
    for (int l = tid; l < LL; l += 512) {
        float v32r = vb[(size_t)l*EE + 32].x;
        #pragma unroll
        for (int u = 0; u < 4; ++u)
            s32[u] = fmaf(p[(u << 11) + l].x, v32r, s32[u]);
    }
    #pragma unroll
    for (int o = 16; o; o >>= 1) {
        #pragma unroll
        for (int u = 0; u < 4; ++u)
            s32[u] += __shfl_xor_sync(0xffffffffu, s32[u], o);
    }
    #pragma unroll
    for (int u = 0; u < 4; ++u) {
        float aR, aI;
        upk2(acc2[u], aR, aI);
        accs[(warp*4 + u)*EE + lane] = make_float2(aR, aI);
        if (lane == 0) accs[(warp*4 + u)*EE + 32] = make_float2(s32[u], 0.f);
    }
    __syncthreads();
    for (int t = tid; t < 4*EE; t += 512) {
        int u = t / EE, e = t - u*EE;
        float ssr = 0.f, ssi = 0.f;
        #pragma unroll
        for (int w = 0; w < 16; ++w) {
            float2 a = accs[(w*4 + u)*EE + e];
            ssr += a.x; ssi += a.y;
        }
        g_upd[((size_t)bh*UU + ug*4 + u)*EE + e] = make_float2(ssr, ssi);
    }
}

// ---------------- K7: scatter + irfft, 4 rows per warp ----------------
__global__ void k_out(float* __restrict__ out)
{
    __shared__ float tc[64], ts[64];
    __shared__ float2 ub[8][EE];
    int tid = threadIdx.x;
    if (tid < 64) {
        float s, c;
        sincospif(tid * (1.0f/32.0f), &s, &c);
        tc[tid] = c; ts[tid] = s;
    }
    __syncthreads();
    int warp = tid >> 5, lane = tid & 31;
    #pragma unroll 1
    for (int i = 0; i < 4; ++i) {
        int r = blockIdx.x * 32 + warp * 4 + i;
        int bh = r >> 11;
        int slot = g_slot[r];
        float* op = out + (size_t)r * DD;
        if (slot < 0) {
            op[lane]      = g_vmt[bh*DD + lane];
            op[lane + 32] = g_vmt[bh*DD + lane + 32];
        } else {
            const float2* X = g_upd + ((size_t)bh*UU + slot)*EE;
            ub[warp][lane] = X[lane];
            if (lane == 0) ub[warp][32] = X[32];
            __syncwarp();
            float a0 = ub[warp][0].x;
            float a32 = ub[warp][32].x;
            float sgn = (lane & 1) ? -a32 : a32;
            float acc1 = a0 + sgn, acc2 = a0 + sgn;
            #pragma unroll
            for (int e = 1; e < 32; ++e) {
                float2 Xe = ub[warp][e];
                int j1 = (e * lane) & 63;
                int j2 = (e * (lane + 32)) & 63;
                acc1 += 2.f * (Xe.x*tc[j1] - Xe.y*ts[j1]);
                acc2 += 2.f * (Xe.x*tc[j2] - Xe.y*ts[j2]);
            }
            op[lane]      = acc1 * (1.0f/64.0f);
            op[lane + 32] = acc2 * (1.0f/64.0f);
            __syncwarp();
        }
    }
}

// ---------------- launch ----------------
extern "C" void kernel_launch(void* const* d_in, const int* in_sizes, int n_in,
                              void* d_out, int out_size)
{
    (void)in_sizes; (void)n_in; (void)out_size;
    const float* q = (const float*)d_in[0];
    const float* k = (const float*)d_in[1];
    const float* v = (const float*)d_in[2];
    const int* isamp = (const int*)d_in[4];
    float* out = (float*)d_out;

    cudaFuncSetAttribute(k_msample, cudaFuncAttributeMaxDynamicSharedMemorySize, MS_SMEM);
    cudaFuncSetAttribute(k_smupd,   cudaFuncAttributeMaxDynamicSharedMemorySize, SMU_SMEM);

    k_rfft     <<<dim3(ROWS/32, 3), 256>>>(q, k, v);
    k_vmt      <<<BHN, 512>>>(v);
    k_msample  <<<dim3(LL/256, BHN), 1024, MS_SMEM>>>(isamp);
    k_topk     <<<BHN, 256>>>();
    k_scores   <<<dim3(4, 4, BHN), 512>>>();
    k_smupd    <<<dim3(10, BHN), 512, SMU_SMEM>>>();
    k_out      <<<ROWS/32, 256>>>(out);
}

// round 17
// speedup vs baseline: 1.0281x; 1.0102x over previous
#include <cuda_runtime.h>
#include <cstdint>
#include <cstddef>

#define BB 8
#define LL 2048
#define HH 8
#define DD 64
#define EE 33
#define UU 40
#define SK 40
#define BHN (BB*HH)
#define ROWS (BHN*LL)

// ---------------- static scratch ----------------
__device__ float2 g_qf [ROWS*EE];
__device__ float2 g_vf [ROWS*EE];
__device__ float4 g_kfC[(size_t)BHN*8*4096];   // [bh][chunk(8)][id*2+half]
__device__ float  g_k32[BHN*LL];
__device__ float  g_M  [ROWS];
__device__ int    g_top [BHN*UU];
__device__ int    g_slot[ROWS];
__device__ float2 g_upd [BHN*UU*EE];
__device__ float  g_vmt[BHN*DD];
__device__ float2 g_big [(size_t)BHN*UU*LL];

__device__ __forceinline__ void cpa16(void* s, const void* g) {
    unsigned sa = (unsigned)__cvta_generic_to_shared(s);
    asm volatile("cp.async.cg.shared.global [%0], [%1], 16;" :: "r"(sa), "l"(g));
}
__device__ __forceinline__ void cp_commit() {
    asm volatile("cp.async.commit_group;" ::: "memory");
}
__device__ __forceinline__ void cp_wait1() {
    asm volatile("cp.async.wait_group 1;" ::: "memory");
}
__device__ __forceinline__ void cp_wait0() {
    asm volatile("cp.async.wait_group 0;" ::: "memory");
}

// ---------------- K1: rfft, 4 rows/warp, register twiddles, shfl mirror ----------------
__global__ void k_rfft(const float* __restrict__ q,
                       const float* __restrict__ k,
                       const float* __restrict__ v)
{
    __shared__ float2 w32t[16], w64t[32];
    int tid = threadIdx.x;
    if (tid < 16) {
        float s, c;
        sincospif(tid * (1.0f/16.0f), &s, &c);
        w32t[tid] = make_float2(c, s);
    } else if (tid < 48) {
        float s, c;
        sincospif((tid - 16) * (1.0f/32.0f), &s, &c);
        w64t[tid - 16] = make_float2(c, s);
    }
    __syncthreads();
    int warp = tid >> 5, lane = tid & 31;
    float2 tw[5];
    #pragma unroll
    for (int s = 0; s < 5; ++s) {
        int hm = 16 >> s;
        tw[s] = w32t[(lane & (hm - 1)) << s];
    }
    int bin = __brev((unsigned)lane) >> 27;
    float2 w64 = w64t[bin];
    int mb   = (32 - bin) & 31;
    int srcl = __brev((unsigned)mb) >> 27;
    int which = blockIdx.y;
    const float* src = (which == 0) ? q : (which == 1) ? k : v;
    float2* out = (which == 0) ? g_qf : g_vf;
    #pragma unroll 1
    for (int i = 0; i < 4; ++i) {
        int r  = blockIdx.x * 32 + warp * 4 + i;
        int l  = r & (LL - 1);
        int bh = r >> 11;
        int b = bh >> 3, h = bh & 7;
        const float2* x2 = (const float2*)(src + (((size_t)b*LL + l)*HH + h) * DD);
        float2 z = x2[lane];
        float zr = z.x, zi = z.y;
        #pragma unroll
        for (int s = 0; s < 5; ++s) {
            int hm = 16 >> s;
            float orr = __shfl_xor_sync(0xffffffffu, zr, hm);
            float oii = __shfl_xor_sync(0xffffffffu, zi, hm);
            float2 w = tw[s];
            float dx = orr - zr, dy = oii - zi;
            float hr = dx*w.x + dy*w.y;
            float hi = dy*w.x - dx*w.y;
            float lr = zr + orr, li = zi + oii;
            bool top = (lane & hm) != 0;
            zr = top ? hr : lr;
            zi = top ? hi : li;
        }
        float Zmr = __shfl_sync(0xffffffffu, zr, srcl);
        float Zmi = __shfl_sync(0xffffffffu, zi, srcl);
        float Zer = 0.5f*(zr + Zmr), Zei = 0.5f*(zi - Zmi);
        float Zor = 0.5f*(zi + Zmi), Zoi = -0.5f*(zr - Zmr);
        float Xr = Zer + w64.x*Zor + w64.y*Zoi;
        float Xi = Zei + w64.x*Zoi - w64.y*Zor;
        if (which == 1) {
            int c = bin >> 2, half = (bin >> 1) & 1;
            float2* kc2 = (float2*)g_kfC;
            size_t idx = ((((size_t)(bh*8 + c)) << 12) + (size_t)l*2 + half)*2 + (bin & 1);
            kc2[idx] = make_float2(Xr, Xi);
            if (bin == 0) g_k32[bh*LL + l] = zr - zi;
        } else {
            out[(size_t)r*EE + bin] = make_float2(Xr, Xi);
            if (bin == 0) out[(size_t)r*EE + 32] = make_float2(zr - zi, 0.f);
        }
    }
}

// ---------------- K2b: time-domain v mean ----------------
__global__ void k_vmt(const float* __restrict__ v)
{
    __shared__ float part[8][64];
    int bh = blockIdx.x, b = bh >> 3, h = bh & 7;
    int tid = threadIdx.x;
    int d = tid & 63, g = tid >> 6;
    const float* base = v + (((size_t)b*LL)*HH + h) * DD + d;
    float acc = 0.f;
    #pragma unroll 8
    for (int i = g; i < LL; i += 8) acc += base[(size_t)i * (HH*DD)];
    part[g][d] = acc;
    __syncthreads();
    if (tid < 64) {
        float s = 0.f;
        #pragma unroll
        for (int g2 = 0; g2 < 8; ++g2) s += part[g2][tid];
        g_vmt[bh*DD + tid] = s * (1.0f/LL);
    }
}

// ---------------- K3: sampled QK -> M (smem keys + staged q) ----------------
#define MS_KBUF   131072
#define MS_SK32   (MS_KBUF)
#define MS_PT     (MS_KBUF + 8192)
#define MS_QS     (MS_KBUF + 8192 + 16384)
#define MS_SMEM   (MS_KBUF + 8192 + 16384 + 10240)
__global__ void __launch_bounds__(1024, 1) k_msample(const int* __restrict__ isamp)
{
    extern __shared__ char sm[];
    float4* kbuf = (float4*)sm;
    float*  sk32 = (float*)(sm + MS_SK32);
    float4* pt   = (float4*)(sm + MS_PT);
    float2* qs   = (float2*)(sm + MS_QS);

    int tid = threadIdx.x;
    int l0  = blockIdx.x * 256;
    int bh  = blockIdx.y;
    int sg  = tid & 3;
    int lq  = tid >> 2;
    int l   = l0 + lq;

    sk32[tid]        = g_k32[bh*LL + tid];
    sk32[tid + 1024] = g_k32[bh*LL + tid + 1024];

    const int* ip = isamp + l*SK + sg*10;
    int ids[10];
    #pragma unroll
    for (int i = 0; i < 10; ++i) ids[i] = ip[i];

    float q32 = g_qf[((size_t)(bh*LL + l))*EE + 32].x;

    const float4* kc = g_kfC + (((size_t)(bh*8)) << 12);
    #pragma unroll
    for (int it = 0; it < 4; ++it) {
        int lin = it*1024 + tid;
        int sw  = lin ^ ((lin >> 3) & 7);
        cpa16(&kbuf[sw], &kc[lin]);
    }
    cp_commit();

    float accR[10], accI[10];
    #pragma unroll
    for (int s = 0; s < 10; ++s) { accR[s] = 0.f; accI[s] = 0.f; }

    int qrow_s = tid >> 2, qbin_s = tid & 3;
    const float2* qsrc = g_qf + (size_t)(bh*LL + l0 + qrow_s)*EE + qbin_s;

    #pragma unroll 1
    for (int c = 0; c < 8; ++c) {
        qs[qrow_s*5 + qbin_s] = qsrc[4*c];
        int cur = (c & 1) << 12;
        if (c < 7) {
            const float4* src = kc + ((size_t)(c+1) << 12);
            int nb = ((c+1) & 1) << 12;
            #pragma unroll
            for (int it = 0; it < 4; ++it) {
                int lin = it*1024 + tid;
                int sw  = lin ^ ((lin >> 3) & 7);
                cpa16(&kbuf[nb + sw], &src[lin]);
            }
            cp_commit();
            cp_wait1();
        } else {
            cp_wait0();
        }
        __syncthreads();
        float2 q0 = qs[lq*5 + 0], q1 = qs[lq*5 + 1], q2 = qs[lq*5 + 2], q3 = qs[lq*5 + 3];
        #pragma unroll
        for (int s = 0; s < 10; ++s) {
            int id = ids[s];
            int p = id << 1, x = (id >> 2) & 7;
            float4 h0 = kbuf[cur + (p ^ x)];
            float4 h1 = kbuf[cur + ((p + 1) ^ x)];
            accR[s] = fmaf(q0.x, h0.x, accR[s]); accR[s] = fmaf(-q0.y, h0.y, accR[s]);
            accI[s] = fmaf(q0.x, h0.y, accI[s]); accI[s] = fmaf( q0.y, h0.x, accI[s]);
            accR[s] = fmaf(q1.x, h0.z, accR[s]); accR[s] = fmaf(-q1.y, h0.w, accR[s]);
            accI[s] = fmaf(q1.x, h0.w, accI[s]); accI[s] = fmaf( q1.y, h0.z, accI[s]);
            accR[s] = fmaf(q2.x, h1.x, accR[s]); accR[s] = fmaf(-q2.y, h1.y, accR[s]);
            accI[s] = fmaf(q2.x, h1.y, accI[s]); accI[s] = fmaf( q2.y, h1.x, accI[s]);
            accR[s] = fmaf(q3.x, h1.z, accR[s]); accR[s] = fmaf(-q3.y, h1.w, accR[s]);
            accI[s] = fmaf(q3.x, h1.w, accI[s]); accI[s] = fmaf( q3.y, h1.z, accI[s]);
        }
        __syncthreads();
    }
    #pragma unroll
    for (int s = 0; s < 10; ++s)
        accR[s] = fmaf(q32, sk32[ids[s]], accR[s]);

    float mr = -3.4e38f, mi = -3.4e38f, sr = 0.f, si = 0.f;
    #pragma unroll
    for (int s = 0; s < 10; ++s) {
        mr = fmaxf(mr, accR[s]); mi = fmaxf(mi, accI[s]);
        sr += accR[s];           si += accI[s];
    }
    pt[sg*256 + lq] = make_float4(mr, mi, sr, si);
    __syncthreads();
    if (tid < 256) {
        float4 a = pt[tid], b = pt[256 + tid], c2 = pt[512 + tid], d = pt[768 + tid];
        float MR = fmaxf(fmaxf(a.x, b.x), fmaxf(c2.x, d.x));
        float MI = fmaxf(fmaxf(a.y, b.y), fmaxf(c2.y, d.y));
        float SR = a.z + b.z + c2.z + d.z;
        float SI = a.w + b.w + c2.w + d.w;
        g_M[(size_t)bh*LL + l0 + tid] = MR + MI - (SR + SI) * (1.0f/LL);
    }
}

// ---------------- K4: top-40 per bh — warp-local select + single-warp merge ----------------
__global__ void __launch_bounds__(256) k_topk()
{
    __shared__ float wlv[8][UU];
    __shared__ int   wli[8][UU];
    int bh = blockIdx.x, tid = threadIdx.x, lane = tid & 31, warp = tid >> 5;
    for (int i = tid; i < LL; i += 256)
        g_slot[bh*LL + i] = -1;

    int base = warp * 256;
    float vals[8];
    #pragma unroll
    for (int k = 0; k < 8; ++k)
        vals[k] = g_M[bh*LL + base + lane + k*32];
    #pragma unroll 1
    for (int u = 0; u < UU; ++u) {
        float best = -3.4e38f; int bk = 0;
        #pragma unroll
        for (int k = 0; k < 8; ++k)
            if (vals[k] > best) { best = vals[k]; bk = k; }
        int bidx = base + lane + bk*32;
        float bv = best; int bi = bidx;
        #pragma unroll
        for (int o = 16; o; o >>= 1) {
            float ov = __shfl_xor_sync(0xffffffffu, bv, o);
            int   oi = __shfl_xor_sync(0xffffffffu, bi, o);
            if (ov > bv || (ov == bv && oi < bi)) { bv = ov; bi = oi; }
        }
        if (bi == bidx) vals[bk] = -3.4e38f;
        if (lane == 0) { wlv[warp][u] = bv; wli[warp][u] = bi; }
    }
    __syncthreads();

    if (warp == 0) {
        int ptr = 0;
        #pragma unroll 1
        for (int u = 0; u < UU; ++u) {
            float hv = (lane < 8) ? wlv[lane][ptr] : -3.4e38f;
            int   hi = (lane < 8) ? wli[lane][ptr] : (1 << 30);
            float rv = hv; int ri = hi;
            #pragma unroll
            for (int o = 4; o; o >>= 1) {
                float ov = __shfl_xor_sync(0xffffffffu, rv, o);
                int   oi = __shfl_xor_sync(0xffffffffu, ri, o);
                if (ov > rv || (ov == rv && oi < ri)) { rv = ov; ri = oi; }
            }
            rv = __shfl_sync(0xffffffffu, rv, 0);
            ri = __shfl_sync(0xffffffffu, ri, 0);
            if (lane < 8 && ri == hi) ptr++;
            if (lane == 0) {
                g_top[bh*UU + u] = ri;
                g_slot[bh*LL + ri] = u;
            }
        }
    }
}

// ---------------- K5: full scores from chunked keys, 10-u register blocked ----------------
__global__ void __launch_bounds__(512) k_scores()
{
    __shared__ float2 shq[10][EE];
    int bh = blockIdx.z;
    int ug = blockIdx.y;
    int jt = blockIdx.x;
    int tid = threadIdx.x;
    for (int t = tid; t < 10*EE; t += 512) {
        int ul = t / EE, e = t - ul*EE;
        int qi = g_top[bh*UU + ug*10 + ul];
        shq[ul][e] = g_qf[((size_t)bh*LL + qi)*EE + e];
    }
    __syncthreads();
    int j = jt*512 + tid;
    float accR[10], accI[10];
    #pragma unroll
    for (int u = 0; u < 10; ++u) { accR[u] = 0.f; accI[u] = 0.f; }
    const float4* kc = g_kfC + (((size_t)(bh*8)) << 12);
    #pragma unroll 1
    for (int c = 0; c < 8; ++c) {
        float4 h0 = kc[((size_t)c << 12) + j*2];
        float4 h1 = kc[((size_t)c << 12) + j*2 + 1];
        #pragma unroll
        for (int u = 0; u < 10; ++u) {
            float2 q0 = shq[u][4*c], q1 = shq[u][4*c+1], q2 = shq[u][4*c+2], q3 = shq[u][4*c+3];
            accR[u] = fmaf(q0.x, h0.x, accR[u]); accR[u] = fmaf(-q0.y, h0.y, accR[u]);
            accI[u] = fmaf(q0.x, h0.y, accI[u]); accI[u] = fmaf( q0.y, h0.x, accI[u]);
            accR[u] = fmaf(q1.x, h0.z, accR[u]); accR[u] = fmaf(-q1.y, h0.w, accR[u]);
            accI[u] = fmaf(q1.x, h0.w, accI[u]); accI[u] = fmaf( q1.y, h0.z, accI[u]);
            accR[u] = fmaf(q2.x, h1.x, accR[u]); accR[u] = fmaf(-q2.y, h1.y, accR[u]);
            accI[u] = fmaf(q2.x, h1.y, accI[u]); accI[u] = fmaf( q2.y, h1.x, accI[u]);
            accR[u] = fmaf(q3.x, h1.z, accR[u]); accR[u] = fmaf(-q3.y, h1.w, accR[u]);
            accI[u] = fmaf(q3.x, h1.w, accI[u]); accI[u] = fmaf( q3.y, h1.z, accI[u]);
        }
    }
    {
        float k32 = g_k32[bh*LL + j];
        #pragma unroll
        for (int u = 0; u < 10; ++u) {
            float2 qv = shq[u][32];
            accR[u] = fmaf(qv.x, k32, accR[u]);
            accI[u] = fmaf(qv.y, k32, accI[u]);
        }
    }
    const float sc = 0.125f;
    #pragma unroll
    for (int u = 0; u < 10; ++u)
        g_big[((size_t)bh*UU + ug*10 + u)*LL + j] = make_float2(accR[u]*sc, accI[u]*sc);
}

// ---------------- K6: fused softmax + upd (4 u per block, 2 blocks/SM) ----------------
#define SMU_SMEM (65536 + 16896 + 128)
__global__ void __launch_bounds__(512) k_smupd()
{
    extern __shared__ char smc[];
    float2* p    = (float2*)smc;
    float2* accs = (float2*)(smc + 65536);
    float2* mxs  = (float2*)(smc + 65536 + 16896);
    int bh = blockIdx.y, ug = blockIdx.x;
    int tid = threadIdx.x, warp = tid >> 5, lane = tid & 31;

    const float2* gb = g_big + ((size_t)bh*UU + ug*4)*LL;
    for (int i = tid; i < 4*LL; i += 512)
        p[i] = gb[i];
    __syncthreads();

    int su = warp >> 2, qt = warp & 3;
    float2* row = p + (su << 11) + (qt << 9);
    float mr = -3.4e38f, mi = -3.4e38f;
    #pragma unroll 8
    for (int k2 = 0; k2 < 16; ++k2) {
        float2 vv = row[lane + k2*32];
        mr = fmaxf(mr, vv.x); mi = fmaxf(mi, vv.y);
    }
    #pragma unroll
    for (int o = 16; o; o >>= 1) {
        mr = fmaxf(mr, __shfl_xor_sync(0xffffffffu, mr, o));
        mi = fmaxf(mi, __shfl_xor_sync(0xffffffffu, mi, o));
    }
    if (lane == 0) mxs[warp] = make_float2(mr, mi);
    __syncthreads();
    {
        float2 a = mxs[su*4], b = mxs[su*4+1], c = mxs[su*4+2], d = mxs[su*4+3];
        mr = fmaxf(fmaxf(a.x, b.x), fmaxf(c.x, d.x));
        mi = fmaxf(fmaxf(a.y, b.y), fmaxf(c.y, d.y));
    }
    __syncthreads();
    float sr = 0.f, si = 0.f;
    #pragma unroll 8
    for (int k2 = 0; k2 < 16; ++k2) {
        float2 vv = row[lane + k2*32];
        float er = __expf(vv.x - mr);
        float ei = __expf(vv.y - mi);
        row[lane + k2*32] = make_float2(er, ei);
        sr += er; si += ei;
    }
    #pragma unroll
    for (int o = 16; o; o >>= 1) {
        sr += __shfl_xor_sync(0xffffffffu, sr, o);
        si += __shfl_xor_sync(0xffffffffu, si, o);
    }
    if (lane == 0) mxs[warp] = make_float2(sr, si);
    __syncthreads();
    {
        float2 a = mxs[su*4], b = mxs[su*4+1], c = mxs[su*4+2], d = mxs[su*4+3];
        float inr = 1.0f / (a.x + b.x + c.x + d.x);
        float ini = 1.0f / (a.y + b.y + c.y + d.y);
        #pragma unroll 8
        for (int k2 = 0; k2 < 16; ++k2) {
            float2 vv = row[lane + k2*32];
            row[lane + k2*32] = make_float2(vv.x * inr, vv.y * ini);
        }
    }
    __syncthreads();

    float aR[4], aI[4];
    #pragma unroll
    for (int u = 0; u < 4; ++u) { aR[u]=0.f; aI[u]=0.f; }
    const float2* vb = g_vf + (size_t)bh*LL*EE;
    for (int l = warp; l < LL; l += 16) {
        float2 v2 = vb[(size_t)l*EE + lane];
        #pragma unroll
        for (int u = 0; u < 4; ++u) {
            float2 pp = p[(u << 11) + l];
            aR[u] = fmaf(pp.x, v2.x, aR[u]);
            aI[u] = fmaf(pp.y, v2.y, aI[u]);
        }
    }
    float s32[4];
    #pragma unroll
    for (int u = 0; u < 4; ++u) s32[u] = 0.f;
    for (int l = tid; l < LL; l += 512) {
        float v32r = vb[(size_t)l*EE + 32].x;
        #pragma unroll
        for (int u = 0; u < 4; ++u)
            s32[u] = fmaf(p[(u << 11) + l].x, v32r, s32[u]);
    }
    #pragma unroll
    for (int o = 16; o; o >>= 1) {
        #pragma unroll
        for (int u = 0; u < 4; ++u)
            s32[u] += __shfl_xor_sync(0xffffffffu, s32[u], o);
    }
    #pragma unroll
    for (int u = 0; u < 4; ++u) {
        accs[(warp*4 + u)*EE + lane] = make_float2(aR[u], aI[u]);
        if (lane == 0) accs[(warp*4 + u)*EE + 32] = make_float2(s32[u], 0.f);
    }
    __syncthreads();
    for (int t = tid; t < 4*EE; t += 512) {
        int u = t / EE, e = t - u*EE;
        float ssr = 0.f, ssi = 0.f;
        #pragma unroll
        for (int w = 0; w < 16; ++w) {
            float2 a = accs[(w*4 + u)*EE + e];
            ssr += a.x; ssi += a.y;
        }
        g_upd[((size_t)bh*UU + ug*4 + u)*EE + e] = make_float2(ssr, ssi);
    }
}

// ---------------- K7: scatter + irfft, 4 rows per warp ----------------
__global__ void k_out(float* __restrict__ out)
{
    __shared__ float tc[64], ts[64];
    __shared__ float2 ub[8][EE];
    int tid = threadIdx.x;
    if (tid < 64) {
        float s, c;
        sincospif(tid * (1.0f/32.0f), &s, &c);
        tc[tid] = c; ts[tid] = s;
    }
    __syncthreads();
    int warp = tid >> 5, lane = tid & 31;
    #pragma unroll 1
    for (int i = 0; i < 4; ++i) {
        int r = blockIdx.x * 32 + warp * 4 + i;
        int bh = r >> 11;
        int slot = g_slot[r];
        float* op = out + (size_t)r * DD;
        if (slot < 0) {
            op[lane]      = g_vmt[bh*DD + lane];
            op[lane + 32] = g_vmt[bh*DD + lane + 32];
        } else {
            const float2* X = g_upd + ((size_t)bh*UU + slot)*EE;
            ub[warp][lane] = X[lane];
            if (lane == 0) ub[warp][32] = X[32];
            __syncwarp();
            float a0 = ub[warp][0].x;
            float a32 = ub[warp][32].x;
            float sgn = (lane & 1) ? -a32 : a32;
            float acc1 = a0 + sgn, acc2 = a0 + sgn;
            #pragma unroll
            for (int e = 1; e < 32; ++e) {
                float2 Xe = ub[warp][e];
                int j1 = (e * lane) & 63;
                int j2 = (e * (lane + 32)) & 63;
                acc1 += 2.f * (Xe.x*tc[j1] - Xe.y*ts[j1]);
                acc2 += 2.f * (Xe.x*tc[j2] - Xe.y*ts[j2]);
            }
            op[lane]      = acc1 * (1.0f/64.0f);
            op[lane + 32] = acc2 * (1.0f/64.0f);
            __syncwarp();
        }
    }
}

// ---------------- launch ----------------
extern "C" void kernel_launch(void* const* d_in, const int* in_sizes, int n_in,
                              void* d_out, int out_size)
{
    (void)in_sizes; (void)n_in; (void)out_size;
    const float* q = (const float*)d_in[0];
    const float* k = (const float*)d_in[1];
    const float* v = (const float*)d_in[2];
    const int* isamp = (const int*)d_in[4];
    float* out = (float*)d_out;

    cudaFuncSetAttribute(k_msample, cudaFuncAttributeMaxDynamicSharedMemorySize, MS_SMEM);
    cudaFuncSetAttribute(k_smupd,   cudaFuncAttributeMaxDynamicSharedMemorySize, SMU_SMEM);

    k_rfft     <<<dim3(ROWS/32, 3), 256>>>(q, k, v);
    k_vmt      <<<BHN, 512>>>(v);
    k_msample  <<<dim3(LL/256, BHN), 1024, MS_SMEM>>>(isamp);
    k_topk     <<<BHN, 256>>>();
    k_scores   <<<dim3(4, 4, BHN), 512>>>();
    k_smupd    <<<dim3(10, BHN), 512, SMU_SMEM>>>();
    k_out      <<<ROWS/32, 256>>>(out);
}